// round 4
// baseline (speedup 1.0000x reference)
#include <cuda_runtime.h>
#include <math.h>

// ---------------------------------------------------------------------------
// Problem constants: B=4, S=1024, E=1024, H=16, DH=64
// ---------------------------------------------------------------------------
#define BB   4
#define SS   1024
#define EE   1024
#define HH   16
#define DH   64
#define NTOK (BB * SS)          // 4096 rows

// ---------------------------------------------------------------------------
// Scratch (static device globals; no allocation allowed anywhere)
// ---------------------------------------------------------------------------
__device__ float g_h    [(size_t)NTOK * EE];          // LN1 output
__device__ float g_qkv  [(size_t)NTOK * 3 * EE];      // fused qkv
__device__ float g_probs[(size_t)BB * HH * SS * SS];  // attention probs (256 MB)
__device__ float g_att  [(size_t)NTOK * EE];          // attn output (pre-proj)
__device__ float g_x1   [(size_t)NTOK * EE];          // x + attn_proj
__device__ float g_h2   [(size_t)NTOK * EE];          // LN2 output
__device__ float g_fc   [(size_t)NTOK * 4 * EE];      // gelu(fc) (64 MB)

// Device-side scratch resolver: id < 0 means "use the external pointer".
__device__ __forceinline__ float* scratch_ptr(int id) {
    switch (id) {
        case 0:  return g_h;
        case 1:  return g_qkv;
        case 2:  return g_probs;
        case 3:  return g_att;
        case 4:  return g_x1;
        case 5:  return g_h2;
        default: return g_fc;
    }
}
__device__ __forceinline__ const float* resolve_c(const float* ext, int id, long off) {
    return (id >= 0 ? (const float*)scratch_ptr(id) : ext) + off;
}
__device__ __forceinline__ float* resolve_m(float* ext, int id) {
    return id >= 0 ? scratch_ptr(id) : ext;
}

// ---------------------------------------------------------------------------
// GELU (tanh approx, matches reference)
// ---------------------------------------------------------------------------
__device__ __forceinline__ float gelu_f(float v) {
    const float c = 0.7978845608028654f;
    float t = tanhf(c * (v + 0.044715f * v * v * v));
    return 0.5f * v * (1.f + t);
}

enum { EPI_NONE = 0, EPI_BIAS = 1, EPI_BIAS_RES = 2, EPI_GELU = 3, EPI_SCORES = 4 };

// ---------------------------------------------------------------------------
// Tiled SGEMM: C[M,N] = A[M,K] * op(B) (+ epilogue)
//   B_NT=true : B stored [N,K] row-major (C = A * B^T)   — weight layouts
//   B_NT=false: B stored [K,N] row-major (C = A * B)     — probs @ v
// 64x64 tile, BK=16, 256 threads, 4x4 micro-tile per thread.
// Batch via grid.z: offset = (z/Hdim)*outer + (z%Hdim)*inner for A/B/C.
// All M,N multiples of 64 and K multiples of 16 (guaranteed by call sites).
// ---------------------------------------------------------------------------
template <int EPI, bool B_NT>
__global__ __launch_bounds__(256)
void gemm_kernel(const float* __restrict__ Ax, int Aid, long Aoff,
                 const float* __restrict__ Bx, int Bid, long Boff,
                 float* __restrict__ Cx, int Cid,
                 int K, int lda, int ldb, int ldc,
                 const float* __restrict__ bias,
                 const float* __restrict__ Rx, int Rid, int ldres,
                 long aOuter, long aInner, long bOuter, long bInner,
                 long cOuter, long cInner, int Hdim, float scale)
{
    const float* A = resolve_c(Ax, Aid, Aoff);
    const float* B = resolve_c(Bx, Bid, Boff);
    float*       C = resolve_m(Cx, Cid);

    int z  = blockIdx.z;
    int zo = z / Hdim, zi = z - zo * Hdim;
    A += (size_t)zo * aOuter + (size_t)zi * aInner;
    B += (size_t)zo * bOuter + (size_t)zi * bInner;
    C += (size_t)zo * cOuter + (size_t)zi * cInner;

    __shared__ float As[16][64];
    __shared__ float Bs[16][64];

    int tid = threadIdx.x;
    int tx = tid & 15, ty = tid >> 4;
    int bm = blockIdx.y * 64, bn = blockIdx.x * 64;

    float acc[4][4] = {};

    const float* Ab = A + (size_t)bm * lda;

    for (int k0 = 0; k0 < K; k0 += 16) {
        {
            int r = tid >> 2, c4 = tid & 3;
            float4 av = *(const float4*)(Ab + (size_t)r * lda + k0 + c4 * 4);
            As[c4 * 4 + 0][r] = av.x; As[c4 * 4 + 1][r] = av.y;
            As[c4 * 4 + 2][r] = av.z; As[c4 * 4 + 3][r] = av.w;
            if (B_NT) {
                float4 bv = *(const float4*)(B + (size_t)(bn + r) * ldb + k0 + c4 * 4);
                Bs[c4 * 4 + 0][r] = bv.x; Bs[c4 * 4 + 1][r] = bv.y;
                Bs[c4 * 4 + 2][r] = bv.z; Bs[c4 * 4 + 3][r] = bv.w;
            } else {
                int br = tid >> 4, bc = tid & 15;
                float4 bv = *(const float4*)(B + (size_t)(k0 + br) * ldb + bn + bc * 4);
                *(float4*)&Bs[br][bc * 4] = bv;
            }
        }
        __syncthreads();
#pragma unroll
        for (int kk = 0; kk < 16; kk++) {
            float4 a4 = *(const float4*)&As[kk][ty * 4];
            float4 b4 = *(const float4*)&Bs[kk][tx * 4];
            float a[4] = {a4.x, a4.y, a4.z, a4.w};
            float b[4] = {b4.x, b4.y, b4.z, b4.w};
#pragma unroll
            for (int i = 0; i < 4; i++)
#pragma unroll
                for (int j = 0; j < 4; j++)
                    acc[i][j] = fmaf(a[i], b[j], acc[i][j]);
        }
        __syncthreads();
    }

    // Epilogue
    int col = bn + tx * 4;
    float4 bi4 = {0.f, 0.f, 0.f, 0.f};
    if (EPI == EPI_BIAS || EPI == EPI_BIAS_RES || EPI == EPI_GELU)
        bi4 = *(const float4*)(bias + col);
    const float* R = (EPI == EPI_BIAS_RES) ? resolve_c(Rx, Rid, 0) : nullptr;

#pragma unroll
    for (int i = 0; i < 4; i++) {
        int row = bm + ty * 4 + i;
        float v[4] = {acc[i][0], acc[i][1], acc[i][2], acc[i][3]};
        if (EPI == EPI_BIAS || EPI == EPI_BIAS_RES || EPI == EPI_GELU) {
            v[0] += bi4.x; v[1] += bi4.y; v[2] += bi4.z; v[3] += bi4.w;
        }
        if (EPI == EPI_BIAS_RES) {
            float4 r4 = *(const float4*)(R + (size_t)row * ldres + col);
            v[0] += r4.x; v[1] += r4.y; v[2] += r4.z; v[3] += r4.w;
        }
        if (EPI == EPI_GELU) {
#pragma unroll
            for (int j = 0; j < 4; j++) v[j] = gelu_f(v[j]);
        }
        if (EPI == EPI_SCORES) {
#pragma unroll
            for (int j = 0; j < 4; j++)
                v[j] = (col + j <= row) ? v[j] * scale : -INFINITY;
        }
        float4 o = {v[0], v[1], v[2], v[3]};
        *(float4*)(C + (size_t)row * ldc + col) = o;
    }
}

// ---------------------------------------------------------------------------
// LayerNorm: one block per row of 1024 (256 threads, float4 each)
// ---------------------------------------------------------------------------
__global__ __launch_bounds__(256)
void ln_kernel(const float* __restrict__ xx, int xid,
               const float* __restrict__ g, const float* __restrict__ bt,
               int outid)
{
    const float* x = resolve_c(xx, xid, 0);
    float* out = scratch_ptr(outid);
    int row = blockIdx.x;
    const float* xr = x + (size_t)row * EE;
    int t = threadIdx.x;
    float4 v = *(const float4*)(xr + t * 4);
    float s  = v.x + v.y + v.z + v.w;
    float sq = v.x * v.x + v.y * v.y + v.z * v.z + v.w * v.w;
#pragma unroll
    for (int o = 16; o; o >>= 1) {
        s  += __shfl_xor_sync(0xffffffffu, s, o);
        sq += __shfl_xor_sync(0xffffffffu, sq, o);
    }
    __shared__ float ss[8], sqs[8];
    __shared__ float mu_s, rs_s;
    int w = t >> 5;
    if ((t & 31) == 0) { ss[w] = s; sqs[w] = sq; }
    __syncthreads();
    if (t == 0) {
        float S1 = 0.f, S2 = 0.f;
        for (int i = 0; i < 8; i++) { S1 += ss[i]; S2 += sqs[i]; }
        float mu  = S1 * (1.f / EE);
        float var = S2 * (1.f / EE) - mu * mu;
        mu_s = mu;
        rs_s = rsqrtf(var + 1e-5f);
    }
    __syncthreads();
    float mu = mu_s, rs = rs_s;
    float4 g4 = *(const float4*)(g + t * 4);
    float4 b4 = *(const float4*)(bt + t * 4);
    float4 o;
    o.x = (v.x - mu) * rs * g4.x + b4.x;
    o.y = (v.y - mu) * rs * g4.y + b4.y;
    o.z = (v.z - mu) * rs * g4.z + b4.z;
    o.w = (v.w - mu) * rs * g4.w + b4.w;
    *(float4*)(out + (size_t)row * EE + t * 4) = o;
}

// ---------------------------------------------------------------------------
// Row softmax in-place over rows of length 1024 (one block per row) on g_probs
// ---------------------------------------------------------------------------
__global__ __launch_bounds__(256)
void softmax_kernel()
{
    float* pr = g_probs + (size_t)blockIdx.x * SS;
    int t = threadIdx.x;
    float4 v = *(const float4*)(pr + t * 4);
    float m = fmaxf(fmaxf(v.x, v.y), fmaxf(v.z, v.w));
#pragma unroll
    for (int o = 16; o; o >>= 1) m = fmaxf(m, __shfl_xor_sync(0xffffffffu, m, o));
    __shared__ float sm[8];
    __shared__ float mx_s, inv_s;
    int w = t >> 5;
    if ((t & 31) == 0) sm[w] = m;
    __syncthreads();
    if (t == 0) {
        float M = sm[0];
        for (int i = 1; i < 8; i++) M = fmaxf(M, sm[i]);
        mx_s = M;
    }
    __syncthreads();
    float M = mx_s;
    float4 e;
    e.x = __expf(v.x - M); e.y = __expf(v.y - M);
    e.z = __expf(v.z - M); e.w = __expf(v.w - M);
    float s = e.x + e.y + e.z + e.w;
#pragma unroll
    for (int o = 16; o; o >>= 1) s += __shfl_xor_sync(0xffffffffu, s, o);
    if ((t & 31) == 0) sm[w] = s;
    __syncthreads();
    if (t == 0) {
        float S = 0.f;
        for (int i = 0; i < 8; i++) S += sm[i];
        inv_s = 1.f / S;
    }
    __syncthreads();
    float inv = inv_s;
    e.x *= inv; e.y *= inv; e.z *= inv; e.w *= inv;
    *(float4*)(pr + t * 4) = e;
}

// ---------------------------------------------------------------------------
// att_weights[b,q,c] = mean over heads of g_probs[b,h,q,c]
// ---------------------------------------------------------------------------
__global__ __launch_bounds__(256)
void mean_heads_kernel(float* __restrict__ out)
{
    size_t i  = (size_t)blockIdx.x * blockDim.x + threadIdx.x; // float4 index
    int c4 = (int)(i & 255);
    int q  = (int)((i >> 8) & 1023);
    int b  = (int)(i >> 18);
    const float* base = g_probs + (((size_t)b * HH) * SS + q) * SS + c4 * 4;
    float4 acc = {0.f, 0.f, 0.f, 0.f};
#pragma unroll
    for (int h = 0; h < HH; h++) {
        float4 p = *(const float4*)(base + (size_t)h * SS * SS);
        acc.x += p.x; acc.y += p.y; acc.z += p.z; acc.w += p.w;
    }
    const float inv = 1.f / HH;
    acc.x *= inv; acc.y *= inv; acc.z *= inv; acc.w *= inv;
    *(float4*)(out + i * 4) = acc;
}

// ---------------------------------------------------------------------------
// kernel_launch
// Inputs (metadata order): x, causal_mask, ln1_g, ln1_b, ln2_g, ln2_b,
//   w_in, b_in, w_out, b_out, w_fc, b_fc, w_proj, b_proj
// Output: [x (4096*1024 f32)] then [att_weights (4*1024*1024 f32)]
// ---------------------------------------------------------------------------
extern "C" void kernel_launch(void* const* d_in, const int* in_sizes, int n_in,
                              void* d_out, int out_size)
{
    const float* x     = (const float*)d_in[0];
    const float* ln1g  = (const float*)d_in[2];
    const float* ln1b  = (const float*)d_in[3];
    const float* ln2g  = (const float*)d_in[4];
    const float* ln2b  = (const float*)d_in[5];
    const float* w_in  = (const float*)d_in[6];
    const float* b_in  = (const float*)d_in[7];
    const float* w_out = (const float*)d_in[8];
    const float* b_out = (const float*)d_in[9];
    const float* w_fc  = (const float*)d_in[10];
    const float* b_fc  = (const float*)d_in[11];
    const float* w_proj= (const float*)d_in[12];
    const float* b_proj= (const float*)d_in[13];

    float* outx = (float*)d_out;
    float* outw = outx + (size_t)NTOK * EE;

    const float scale = 0.125f; // 1/sqrt(64)

    // Scratch ids: 0=g_h 1=g_qkv 2=g_probs 3=g_att 4=g_x1 5=g_h2 6=g_fc

    // 1) h = LN1(x)
    ln_kernel<<<NTOK, 256>>>(x, -1, ln1g, ln1b, 0);

    // 2) qkv = h @ w_in^T + b_in    [4096 x 3072]
    gemm_kernel<EPI_BIAS, true><<<dim3(3 * EE / 64, NTOK / 64, 1), 256>>>(
        nullptr, 0, 0,  w_in, -1, 0,  nullptr, 1,
        EE, EE, EE, 3 * EE, b_in, nullptr, -1, 0,
        0, 0, 0, 0, 0, 0, 1, 0.f);

    // 3) scores = scale * q k^T + causal  -> probs buffer  (batched over b,h)
    gemm_kernel<EPI_SCORES, true><<<dim3(SS / 64, SS / 64, BB * HH), 256>>>(
        nullptr, 1, 0,  nullptr, 1, EE,  nullptr, 2,
        DH, 3 * EE, 3 * EE, SS, nullptr, nullptr, -1, 0,
        (long)SS * 3 * EE, DH, (long)SS * 3 * EE, DH,
        (long)HH * SS * SS, (long)SS * SS, HH, scale);

    // 4) softmax rows
    softmax_kernel<<<BB * HH * SS, 256>>>();

    // 5) att_weights = mean over heads
    mean_heads_kernel<<<(BB * SS * SS / 4) / 256, 256>>>(outw);

    // 6) att = probs @ v   (batched over b,h; B stored [K,N])
    gemm_kernel<EPI_NONE, false><<<dim3(DH / 64, SS / 64, BB * HH), 256>>>(
        nullptr, 2, 0,  nullptr, 1, 2 * EE,  nullptr, 3,
        SS, SS, 3 * EE, EE, nullptr, nullptr, -1, 0,
        (long)HH * SS * SS, (long)SS * SS, (long)SS * 3 * EE, DH,
        (long)SS * EE, DH, HH, 0.f);

    // 7) x1 = x + att @ w_out^T + b_out
    gemm_kernel<EPI_BIAS_RES, true><<<dim3(EE / 64, NTOK / 64, 1), 256>>>(
        nullptr, 3, 0,  w_out, -1, 0,  nullptr, 4,
        EE, EE, EE, EE, b_out, x, -1, EE,
        0, 0, 0, 0, 0, 0, 1, 0.f);

    // 8) h2 = LN2(x1)
    ln_kernel<<<NTOK, 256>>>(nullptr, 4, ln2g, ln2b, 5);

    // 9) fc = gelu(h2 @ w_fc^T + b_fc)   [4096 x 4096]
    gemm_kernel<EPI_GELU, true><<<dim3(4 * EE / 64, NTOK / 64, 1), 256>>>(
        nullptr, 5, 0,  w_fc, -1, 0,  nullptr, 6,
        EE, EE, EE, 4 * EE, b_fc, nullptr, -1, 0,
        0, 0, 0, 0, 0, 0, 1, 0.f);

    // 10) out_x = x1 + fc @ w_proj^T + b_proj
    gemm_kernel<EPI_BIAS_RES, true><<<dim3(EE / 64, NTOK / 64, 1), 256>>>(
        nullptr, 6, 0,  w_proj, -1, 0,  outx, -1,
        4 * EE, 4 * EE, 4 * EE, EE, b_proj, nullptr, 4, EE,
        0, 0, 0, 0, 0, 0, 1, 0.f);
}

// round 5
// speedup vs baseline: 2.9626x; 2.9626x over previous
#include <cuda_runtime.h>
#include <math.h>
#include <stdint.h>

// ---------------------------------------------------------------------------
// Problem constants: B=4, S=1024, E=1024, H=16, DH=64
// ---------------------------------------------------------------------------
#define BB   4
#define SS   1024
#define EE   1024
#define HH   16
#define DH   64
#define NTOK (BB * SS)          // 4096 rows

// ---------------------------------------------------------------------------
// Scratch (static device globals; no allocation allowed anywhere)
// ---------------------------------------------------------------------------
__device__ float g_h    [(size_t)NTOK * EE];
__device__ float g_qkv  [(size_t)NTOK * 3 * EE];
__device__ float g_probs[(size_t)BB * HH * SS * SS];
__device__ float g_att  [(size_t)NTOK * EE];
__device__ float g_x1   [(size_t)NTOK * EE];
__device__ float g_h2   [(size_t)NTOK * EE];
__device__ float g_fc   [(size_t)NTOK * 4 * EE];

__device__ __forceinline__ float* scratch_ptr(int id) {
    switch (id) {
        case 0:  return g_h;
        case 1:  return g_qkv;
        case 2:  return g_probs;
        case 3:  return g_att;
        case 4:  return g_x1;
        case 5:  return g_h2;
        default: return g_fc;
    }
}
__device__ __forceinline__ const float* resolve_c(const float* ext, int id, long off) {
    return (id >= 0 ? (const float*)scratch_ptr(id) : ext) + off;
}
__device__ __forceinline__ float* resolve_m(float* ext, int id) {
    return id >= 0 ? scratch_ptr(id) : ext;
}

__device__ __forceinline__ float gelu_f(float v) {
    const float c = 0.7978845608028654f;
    float t = tanhf(c * (v + 0.044715f * v * v * v));
    return 0.5f * v * (1.f + t);
}

__device__ __forceinline__ uint32_t f2tf32(float f) {
    uint32_t u;
    asm("cvt.rna.tf32.f32 %0, %1;" : "=r"(u) : "f"(f));
    return u;
}

__device__ __forceinline__ void mma_tf32(float* c, const uint32_t* a, const uint32_t* b) {
    asm volatile(
        "mma.sync.aligned.m16n8k8.row.col.f32.tf32.tf32.f32 "
        "{%0,%1,%2,%3}, {%4,%5,%6,%7}, {%8,%9}, {%0,%1,%2,%3};"
        : "+f"(c[0]), "+f"(c[1]), "+f"(c[2]), "+f"(c[3])
        : "r"(a[0]), "r"(a[1]), "r"(a[2]), "r"(a[3]), "r"(b[0]), "r"(b[1]));
}

enum { EPI_NONE = 0, EPI_BIAS = 1, EPI_BIAS_RES = 2, EPI_GELU = 3, EPI_SCORES = 4 };

// ---------------------------------------------------------------------------
// tf32 tensor-core GEMM: C[M,N] = A[M,K] * op(B) (+ epilogue)
//   B_NT=true : B stored [N,K] row-major (C = A * B^T)
//   B_NT=false: B stored [K,N] row-major (C = A * B)
// Block tile BM x BN x 32, 256 threads (8 warps = WARPS_M x WARPS_N),
// warp tile (BM/WARPS_M) x (BN/WARPS_N), m16n8k8 fragments.
// TRI_K: truncate K-loop at bm+BM (PV: probs are zero above the diagonal).
// EPI_SCORES: blocks fully above the diagonal skip the mainloop.
// ---------------------------------------------------------------------------
template <int BM, int BN, int WARPS_M, int WARPS_N, int EPI, bool B_NT, bool TRI_K>
__global__ __launch_bounds__(256)
void mma_gemm(const float* __restrict__ Ax, int Aid, long Aoff,
              const float* __restrict__ Bx, int Bid, long Boff,
              float* __restrict__ Cx, int Cid,
              int K, int lda, int ldb, int ldc,
              const float* __restrict__ bias,
              const float* __restrict__ Rx, int Rid, int ldres,
              long aOuter, long aInner, long bOuter, long bInner,
              long cOuter, long cInner, int Hdim, float scale)
{
    constexpr int BK = 32;
    constexpr int WM = BM / WARPS_M, WN = BN / WARPS_N;
    constexpr int MF = WM / 16, NF = WN / 8;
    constexpr int AP = BM + 5;
    constexpr int BP = B_NT ? (BN + 5) : (BN + 8);
    constexpr int ACOPY = BM / 32;      // (BM*BK)/(4*256)
    constexpr int BCOPY = BN / 32;

    const float* A = resolve_c(Ax, Aid, Aoff);
    const float* B = resolve_c(Bx, Bid, Boff);
    float*       C = resolve_m(Cx, Cid);

    int z  = blockIdx.z;
    int zo = z / Hdim, zi = z - zo * Hdim;
    A += (size_t)zo * aOuter + (size_t)zi * aInner;
    B += (size_t)zo * bOuter + (size_t)zi * bInner;
    C += (size_t)zo * cOuter + (size_t)zi * cInner;

    __shared__ __align__(16) uint32_t As[BK][AP];
    __shared__ __align__(16) uint32_t Bs[BK][BP];

    int tid  = threadIdx.x;
    int wid  = tid >> 5, lane = tid & 31;
    int g    = lane >> 2, tig = lane & 3;
    int wm   = (wid / WARPS_N) * WM;
    int wn   = (wid % WARPS_N) * WN;
    int bm   = blockIdx.y * BM, bn = blockIdx.x * BN;

    float acc[MF][NF][4] = {};

    bool fully_masked = (EPI == EPI_SCORES) && (bn >= bm + BM);
    int  Kend = TRI_K ? min(K, bm + BM) : K;

    if (!fully_masked) {
        const float* Ag = A + (size_t)bm * lda;
        const float* BgNT = B + (size_t)bn * ldb;

        for (int k0 = 0; k0 < Kend; k0 += BK) {
            // ---- load A tile [BM x BK] -> As[k][m] (tf32) ----
#pragma unroll
            for (int i = 0; i < ACOPY; i++) {
                int idx = tid + i * 256;
                int m = idx >> 3, kq = idx & 7;
                float4 v = *(const float4*)(Ag + (size_t)m * lda + k0 + kq * 4);
                As[kq * 4 + 0][m] = f2tf32(v.x);
                As[kq * 4 + 1][m] = f2tf32(v.y);
                As[kq * 4 + 2][m] = f2tf32(v.z);
                As[kq * 4 + 3][m] = f2tf32(v.w);
            }
            // ---- load B tile -> Bs[k][n] (tf32) ----
            if (B_NT) {
#pragma unroll
                for (int i = 0; i < BCOPY; i++) {
                    int idx = tid + i * 256;
                    int n = idx >> 3, kq = idx & 7;
                    float4 v = *(const float4*)(BgNT + (size_t)n * ldb + k0 + kq * 4);
                    Bs[kq * 4 + 0][n] = f2tf32(v.x);
                    Bs[kq * 4 + 1][n] = f2tf32(v.y);
                    Bs[kq * 4 + 2][n] = f2tf32(v.z);
                    Bs[kq * 4 + 3][n] = f2tf32(v.w);
                }
            } else {
                constexpr int NQ = BN / 4;
#pragma unroll
                for (int i = 0; i < BCOPY; i++) {
                    int idx = tid + i * 256;
                    int k = idx / NQ, nq = idx % NQ;
                    float4 v = *(const float4*)(B + (size_t)(k0 + k) * ldb + bn + nq * 4);
                    uint4 u;
                    u.x = f2tf32(v.x); u.y = f2tf32(v.y);
                    u.z = f2tf32(v.z); u.w = f2tf32(v.w);
                    *(uint4*)&Bs[k][nq * 4] = u;
                }
            }
            __syncthreads();

#pragma unroll
            for (int kk = 0; kk < BK; kk += 8) {
                uint32_t af[MF][4], bf[NF][2];
#pragma unroll
                for (int mf = 0; mf < MF; mf++) {
                    int mb = wm + mf * 16 + g;
                    af[mf][0] = As[kk + tig    ][mb];
                    af[mf][1] = As[kk + tig    ][mb + 8];
                    af[mf][2] = As[kk + tig + 4][mb];
                    af[mf][3] = As[kk + tig + 4][mb + 8];
                }
#pragma unroll
                for (int nf = 0; nf < NF; nf++) {
                    int nb = wn + nf * 8 + g;
                    bf[nf][0] = Bs[kk + tig    ][nb];
                    bf[nf][1] = Bs[kk + tig + 4][nb];
                }
#pragma unroll
                for (int mf = 0; mf < MF; mf++)
#pragma unroll
                    for (int nf = 0; nf < NF; nf++)
                        mma_tf32(acc[mf][nf], af[mf], bf[nf]);
            }
            __syncthreads();
        }
    }

    // ---- epilogue ----
    const float* R = (EPI == EPI_BIAS_RES) ? resolve_c(Rx, Rid, 0) : nullptr;

#pragma unroll
    for (int mf = 0; mf < MF; mf++) {
#pragma unroll
        for (int nf = 0; nf < NF; nf++) {
            int r0 = bm + wm + mf * 16 + g;
            int r1 = r0 + 8;
            int c  = bn + wn + nf * 8 + tig * 2;
            float v0 = acc[mf][nf][0], v1 = acc[mf][nf][1];
            float v2 = acc[mf][nf][2], v3 = acc[mf][nf][3];
            if (EPI == EPI_BIAS || EPI == EPI_BIAS_RES || EPI == EPI_GELU) {
                float b0 = bias[c], b1 = bias[c + 1];
                v0 += b0; v1 += b1; v2 += b0; v3 += b1;
            }
            if (EPI == EPI_BIAS_RES) {
                float2 ra = *(const float2*)(R + (size_t)r0 * ldres + c);
                float2 rb = *(const float2*)(R + (size_t)r1 * ldres + c);
                v0 += ra.x; v1 += ra.y; v2 += rb.x; v3 += rb.y;
            }
            if (EPI == EPI_GELU) {
                v0 = gelu_f(v0); v1 = gelu_f(v1);
                v2 = gelu_f(v2); v3 = gelu_f(v3);
            }
            if (EPI == EPI_SCORES) {
                v0 = (c     <= r0) ? v0 * scale : -INFINITY;
                v1 = (c + 1 <= r0) ? v1 * scale : -INFINITY;
                v2 = (c     <= r1) ? v2 * scale : -INFINITY;
                v3 = (c + 1 <= r1) ? v3 * scale : -INFINITY;
            }
            float2 oa = {v0, v1}, ob = {v2, v3};
            *(float2*)(C + (size_t)r0 * ldc + c) = oa;
            *(float2*)(C + (size_t)r1 * ldc + c) = ob;
        }
    }
}

// ---------------------------------------------------------------------------
// LayerNorm: one block per row of 1024 (256 threads, float4 each)
// ---------------------------------------------------------------------------
__global__ __launch_bounds__(256)
void ln_kernel(const float* __restrict__ xx, int xid,
               const float* __restrict__ g, const float* __restrict__ bt,
               int outid)
{
    const float* x = resolve_c(xx, xid, 0);
    float* out = scratch_ptr(outid);
    int row = blockIdx.x;
    const float* xr = x + (size_t)row * EE;
    int t = threadIdx.x;
    float4 v = *(const float4*)(xr + t * 4);
    float s  = v.x + v.y + v.z + v.w;
    float sq = v.x * v.x + v.y * v.y + v.z * v.z + v.w * v.w;
#pragma unroll
    for (int o = 16; o; o >>= 1) {
        s  += __shfl_xor_sync(0xffffffffu, s, o);
        sq += __shfl_xor_sync(0xffffffffu, sq, o);
    }
    __shared__ float ss[8], sqs[8];
    __shared__ float mu_s, rs_s;
    int w = t >> 5;
    if ((t & 31) == 0) { ss[w] = s; sqs[w] = sq; }
    __syncthreads();
    if (t == 0) {
        float S1 = 0.f, S2 = 0.f;
        for (int i = 0; i < 8; i++) { S1 += ss[i]; S2 += sqs[i]; }
        float mu  = S1 * (1.f / EE);
        float var = S2 * (1.f / EE) - mu * mu;
        mu_s = mu;
        rs_s = rsqrtf(var + 1e-5f);
    }
    __syncthreads();
    float mu = mu_s, rs = rs_s;
    float4 g4 = *(const float4*)(g + t * 4);
    float4 b4 = *(const float4*)(bt + t * 4);
    float4 o;
    o.x = (v.x - mu) * rs * g4.x + b4.x;
    o.y = (v.y - mu) * rs * g4.y + b4.y;
    o.z = (v.z - mu) * rs * g4.z + b4.z;
    o.w = (v.w - mu) * rs * g4.w + b4.w;
    *(float4*)(out + (size_t)row * EE + t * 4) = o;
}

// ---------------------------------------------------------------------------
// Row softmax in-place over rows of length 1024 (one block per row) on g_probs
// ---------------------------------------------------------------------------
__global__ __launch_bounds__(256)
void softmax_kernel()
{
    float* pr = g_probs + (size_t)blockIdx.x * SS;
    int t = threadIdx.x;
    float4 v = *(const float4*)(pr + t * 4);
    float m = fmaxf(fmaxf(v.x, v.y), fmaxf(v.z, v.w));
#pragma unroll
    for (int o = 16; o; o >>= 1) m = fmaxf(m, __shfl_xor_sync(0xffffffffu, m, o));
    __shared__ float sm[8];
    __shared__ float mx_s, inv_s;
    int w = t >> 5;
    if ((t & 31) == 0) sm[w] = m;
    __syncthreads();
    if (t == 0) {
        float M = sm[0];
        for (int i = 1; i < 8; i++) M = fmaxf(M, sm[i]);
        mx_s = M;
    }
    __syncthreads();
    float M = mx_s;
    float4 e;
    e.x = __expf(v.x - M); e.y = __expf(v.y - M);
    e.z = __expf(v.z - M); e.w = __expf(v.w - M);
    float s = e.x + e.y + e.z + e.w;
#pragma unroll
    for (int o = 16; o; o >>= 1) s += __shfl_xor_sync(0xffffffffu, s, o);
    if ((t & 31) == 0) sm[w] = s;
    __syncthreads();
    if (t == 0) {
        float S = 0.f;
        for (int i = 0; i < 8; i++) S += sm[i];
        inv_s = 1.f / S;
    }
    __syncthreads();
    float inv = inv_s;
    e.x *= inv; e.y *= inv; e.z *= inv; e.w *= inv;
    *(float4*)(pr + t * 4) = e;
}

// ---------------------------------------------------------------------------
// att_weights[b,q,c] = mean over heads of g_probs[b,h,q,c]
// ---------------------------------------------------------------------------
__global__ __launch_bounds__(256)
void mean_heads_kernel(float* __restrict__ out)
{
    size_t i  = (size_t)blockIdx.x * blockDim.x + threadIdx.x;
    int c4 = (int)(i & 255);
    int q  = (int)((i >> 8) & 1023);
    int b  = (int)(i >> 18);
    const float* base = g_probs + (((size_t)b * HH) * SS + q) * SS + c4 * 4;
    float4 acc = {0.f, 0.f, 0.f, 0.f};
#pragma unroll
    for (int h = 0; h < HH; h++) {
        float4 p = *(const float4*)(base + (size_t)h * SS * SS);
        acc.x += p.x; acc.y += p.y; acc.z += p.z; acc.w += p.w;
    }
    const float inv = 1.f / HH;
    acc.x *= inv; acc.y *= inv; acc.z *= inv; acc.w *= inv;
    *(float4*)(out + i * 4) = acc;
}

// ---------------------------------------------------------------------------
// kernel_launch
// Inputs: x, causal_mask, ln1_g, ln1_b, ln2_g, ln2_b,
//   w_in, b_in, w_out, b_out, w_fc, b_fc, w_proj, b_proj
// Output: [x (4096*1024 f32)] then [att_weights (4*1024*1024 f32)]
// ---------------------------------------------------------------------------
extern "C" void kernel_launch(void* const* d_in, const int* in_sizes, int n_in,
                              void* d_out, int out_size)
{
    const float* x     = (const float*)d_in[0];
    const float* ln1g  = (const float*)d_in[2];
    const float* ln1b  = (const float*)d_in[3];
    const float* ln2g  = (const float*)d_in[4];
    const float* ln2b  = (const float*)d_in[5];
    const float* w_in  = (const float*)d_in[6];
    const float* b_in  = (const float*)d_in[7];
    const float* w_out = (const float*)d_in[8];
    const float* b_out = (const float*)d_in[9];
    const float* w_fc  = (const float*)d_in[10];
    const float* b_fc  = (const float*)d_in[11];
    const float* w_proj= (const float*)d_in[12];
    const float* b_proj= (const float*)d_in[13];

    float* outx = (float*)d_out;
    float* outw = outx + (size_t)NTOK * EE;

    const float scale = 0.125f; // 1/sqrt(64)

    // Scratch ids: 0=g_h 1=g_qkv 2=g_probs 3=g_att 4=g_x1 5=g_h2 6=g_fc

    // 1) h = LN1(x)
    ln_kernel<<<NTOK, 256>>>(x, -1, ln1g, ln1b, 0);

    // 2) qkv = h @ w_in^T + b_in    [4096 x 3072]
    mma_gemm<128, 128, 2, 4, EPI_BIAS, true, false>
        <<<dim3(3 * EE / 128, NTOK / 128, 1), 256>>>(
        nullptr, 0, 0,  w_in, -1, 0,  nullptr, 1,
        EE, EE, EE, 3 * EE, b_in, nullptr, -1, 0,
        0, 0, 0, 0, 0, 0, 1, 0.f);

    // 3) scores = scale * q k^T + causal  (batched over b,h)
    mma_gemm<128, 128, 2, 4, EPI_SCORES, true, false>
        <<<dim3(SS / 128, SS / 128, BB * HH), 256>>>(
        nullptr, 1, 0,  nullptr, 1, EE,  nullptr, 2,
        DH, 3 * EE, 3 * EE, SS, nullptr, nullptr, -1, 0,
        (long)SS * 3 * EE, DH, (long)SS * 3 * EE, DH,
        (long)HH * SS * SS, (long)SS * SS, HH, scale);

    // 4) softmax rows
    softmax_kernel<<<BB * HH * SS, 256>>>();

    // 5) att_weights = mean over heads
    mean_heads_kernel<<<(BB * SS * SS / 4) / 256, 256>>>(outw);

    // 6) att = probs @ v   (batched over b,h; triangular K)
    mma_gemm<128, 64, 4, 2, EPI_NONE, false, true>
        <<<dim3(1, SS / 128, BB * HH), 256>>>(
        nullptr, 2, 0,  nullptr, 1, 2 * EE,  nullptr, 3,
        SS, SS, 3 * EE, EE, nullptr, nullptr, -1, 0,
        (long)HH * SS * SS, (long)SS * SS, (long)SS * 3 * EE, DH,
        (long)SS * EE, DH, HH, 0.f);

    // 7) x1 = x + att @ w_out^T + b_out
    mma_gemm<128, 128, 2, 4, EPI_BIAS_RES, true, false>
        <<<dim3(EE / 128, NTOK / 128, 1), 256>>>(
        nullptr, 3, 0,  w_out, -1, 0,  nullptr, 4,
        EE, EE, EE, EE, b_out, x, -1, EE,
        0, 0, 0, 0, 0, 0, 1, 0.f);

    // 8) h2 = LN2(x1)
    ln_kernel<<<NTOK, 256>>>(nullptr, 4, ln2g, ln2b, 5);

    // 9) fc = gelu(h2 @ w_fc^T + b_fc)   [4096 x 4096]
    mma_gemm<128, 128, 2, 4, EPI_GELU, true, false>
        <<<dim3(4 * EE / 128, NTOK / 128, 1), 256>>>(
        nullptr, 5, 0,  w_fc, -1, 0,  nullptr, 6,
        EE, EE, EE, 4 * EE, b_fc, nullptr, -1, 0,
        0, 0, 0, 0, 0, 0, 1, 0.f);

    // 10) out_x = x1 + fc @ w_proj^T + b_proj
    mma_gemm<128, 128, 2, 4, EPI_BIAS_RES, true, false>
        <<<dim3(EE / 128, NTOK / 128, 1), 256>>>(
        nullptr, 6, 0,  w_proj, -1, 0,  outx, -1,
        4 * EE, 4 * EE, 4 * EE, EE, b_proj, nullptr, 4, EE,
        0, 0, 0, 0, 0, 0, 1, 0.f);
}

// round 6
// speedup vs baseline: 3.6597x; 1.2353x over previous
#include <cuda_runtime.h>
#include <math.h>
#include <stdint.h>

// ---------------------------------------------------------------------------
// Problem constants: B=4, S=1024, E=1024, H=16, DH=64
// ---------------------------------------------------------------------------
#define BB   4
#define SS   1024
#define EE   1024
#define HH   16
#define DH   64
#define NTOK (BB * SS)          // 4096 rows

// ---------------------------------------------------------------------------
// Scratch (static device globals; no allocation allowed anywhere)
// ---------------------------------------------------------------------------
__device__ float g_h    [(size_t)NTOK * EE];
__device__ float g_qkv  [(size_t)NTOK * 3 * EE];
__device__ float g_probs[(size_t)BB * HH * SS * SS];   // unnormalized exp scores
__device__ float g_att  [(size_t)NTOK * EE];
__device__ float g_x1   [(size_t)NTOK * EE];
__device__ float g_h2   [(size_t)NTOK * EE];
__device__ float g_fc   [(size_t)NTOK * 4 * EE];
__device__ float g_psum [(size_t)BB * HH * SS * 8];    // per-tile partial row sums
__device__ float g_rsum [(size_t)BB * HH * SS];        // row sums of exp scores

__device__ __forceinline__ float* scratch_ptr(int id) {
    switch (id) {
        case 0:  return g_h;
        case 1:  return g_qkv;
        case 2:  return g_probs;
        case 3:  return g_att;
        case 4:  return g_x1;
        case 5:  return g_h2;
        default: return g_fc;
    }
}
__device__ __forceinline__ const float* resolve_c(const float* ext, int id, long off) {
    return (id >= 0 ? (const float*)scratch_ptr(id) : ext) + off;
}
__device__ __forceinline__ float* resolve_m(float* ext, int id) {
    return id >= 0 ? scratch_ptr(id) : ext;
}

__device__ __forceinline__ float gelu_f(float v) {
    const float c = 0.7978845608028654f;
    float t = tanhf(c * (v + 0.044715f * v * v * v));
    return 0.5f * v * (1.f + t);
}

__device__ __forceinline__ uint32_t f2tf32(float f) {
    uint32_t u;
    asm("cvt.rna.tf32.f32 %0, %1;" : "=r"(u) : "f"(f));
    return u;
}

__device__ __forceinline__ void mma_tf32(float* c, const uint32_t* a, const uint32_t* b) {
    asm volatile(
        "mma.sync.aligned.m16n8k8.row.col.f32.tf32.tf32.f32 "
        "{%0,%1,%2,%3}, {%4,%5,%6,%7}, {%8,%9}, {%0,%1,%2,%3};"
        : "+f"(c[0]), "+f"(c[1]), "+f"(c[2]), "+f"(c[3])
        : "r"(a[0]), "r"(a[1]), "r"(a[2]), "r"(a[3]), "r"(b[0]), "r"(b[1]));
}

__device__ __forceinline__ void cp16(void* dst, const void* src) {
    uint32_t d = (uint32_t)__cvta_generic_to_shared(dst);
    asm volatile("cp.async.ca.shared.global [%0], [%1], 16;\n" :: "r"(d), "l"(src));
}
__device__ __forceinline__ void cp_commit() {
    asm volatile("cp.async.commit_group;\n");
}
template <int N>
__device__ __forceinline__ void cp_wait() {
    asm volatile("cp.async.wait_group %0;\n" :: "n"(N));
}

enum { EPI_NONE = 0, EPI_BIAS = 1, EPI_BIAS_RES = 2, EPI_GELU = 3, EPI_EXP = 4, EPI_PV = 5 };

// ---------------------------------------------------------------------------
// tf32 tensor-core GEMM with cp.async double buffering.
//   C[M,N] = A[M,K] * op(B) (+ epilogue)
//   B_NT=true : B stored [N,K] row-major (C = A * B^T)
//   B_NT=false: B stored [K,N] row-major (C = A * B)
// Block tile BM x BN x 16 (2 stages), 256 threads = WARPS_M x WARPS_N warps.
// EPI_EXP: p = exp(scale*s) masked causal, + per-tile partial row sums to
//          g_psum; fully-masked tiles exit immediately (no stores).
// EPI_PV : divide by g_rsum[row] (probs are unnormalized), TRI_K truncation.
// ---------------------------------------------------------------------------
template <int BM, int BN, int WARPS_M, int WARPS_N, int EPI, bool B_NT, bool TRI_K>
__global__ __launch_bounds__(256)
void mma_gemm(const float* __restrict__ Ax, int Aid, long Aoff,
              const float* __restrict__ Bx, int Bid, long Boff,
              float* __restrict__ Cx, int Cid,
              int K, int lda, int ldb, int ldc,
              const float* __restrict__ bias,
              const float* __restrict__ Rx, int Rid, int ldres,
              long aOuter, long aInner, long bOuter, long bInner,
              long cOuter, long cInner, int Hdim, float scale)
{
    constexpr int BK  = 16;
    constexpr int AKP = BK + 4;                     // 20 floats: conflict-free frag LDS
    constexpr int WM = BM / WARPS_M, WN = BN / WARPS_N;
    constexpr int MF = WM / 16, NF = WN / 8;
    constexpr int BD1 = B_NT ? BN : BK;
    constexpr int BD2 = B_NT ? AKP : (BN + 8);
    constexpr int RP1 = (EPI == EPI_EXP) ? WARPS_N : 1;
    constexpr int RP2 = (EPI == EPI_EXP) ? BM : 1;

    int bm = blockIdx.y * BM, bn = blockIdx.x * BN;
    if (EPI == EPI_EXP && bn >= bm + BM) return;    // fully masked: nothing to do

    const float* A = resolve_c(Ax, Aid, Aoff);
    const float* B = resolve_c(Bx, Bid, Boff);
    float*       C = resolve_m(Cx, Cid);

    int z  = blockIdx.z;
    int zo = z / Hdim, zi = z - zo * Hdim;
    A += (size_t)zo * aOuter + (size_t)zi * aInner;
    B += (size_t)zo * bOuter + (size_t)zi * bInner;
    C += (size_t)zo * cOuter + (size_t)zi * cInner;

    __shared__ __align__(16) float As[2][BM][AKP];
    __shared__ __align__(16) float Bs[2][BD1][BD2];
    __shared__ float rowp[RP1][RP2];

    int tid  = threadIdx.x;
    int wid  = tid >> 5, lane = tid & 31;
    int g    = lane >> 2, tig = lane & 3;
    int wm   = (wid / WARPS_N) * WM;
    int wn   = (wid % WARPS_N) * WN;
    int wnIdx = wid % WARPS_N;

    const float* Ag = A + (size_t)bm * lda;
    const float* Bg = B_NT ? (B + (size_t)bn * ldb) : B;

    int Kend = TRI_K ? min(K, bm + BM) : K;
    int T = Kend / BK;

    float acc[MF][NF][4] = {};

    auto loadA = [&](int st, int k0) {
#pragma unroll
        for (int i = 0; i < BM / 64; i++) {
            int c = tid + i * 256;
            int m = c >> 2, k4 = c & 3;
            cp16(&As[st][m][k4 * 4], Ag + (size_t)m * lda + k0 + k4 * 4);
        }
    };
    auto loadB = [&](int st, int k0) {
        if (B_NT) {
#pragma unroll
            for (int i = 0; i < BN / 64; i++) {
                int c = tid + i * 256;
                int n = c >> 2, k4 = c & 3;
                cp16(&Bs[st][n][k4 * 4], Bg + (size_t)n * ldb + k0 + k4 * 4);
            }
        } else {
            constexpr int CPR = BN / 4;
#pragma unroll
            for (int i = 0; i < BN / 64; i++) {
                int c = tid + i * 256;
                int k = c / CPR, n4 = c % CPR;
                cp16(&Bs[st][k][n4 * 4], B + (size_t)(k0 + k) * ldb + bn + n4 * 4);
            }
        }
    };

    loadA(0, 0); loadB(0, 0); cp_commit();

    int buf = 0;
    for (int it = 0; it < T; it++) {
        if (it + 1 < T) {
            loadA(buf ^ 1, (it + 1) * BK);
            loadB(buf ^ 1, (it + 1) * BK);
            cp_commit();
            cp_wait<1>();
        } else {
            cp_wait<0>();
        }
        __syncthreads();

#pragma unroll
        for (int kk = 0; kk < BK; kk += 8) {
            uint32_t af[MF][4], bf[NF][2];
#pragma unroll
            for (int mf = 0; mf < MF; mf++) {
                int mb = wm + mf * 16 + g;
                af[mf][0] = f2tf32(As[buf][mb    ][kk + tig    ]);
                af[mf][1] = f2tf32(As[buf][mb + 8][kk + tig    ]);
                af[mf][2] = f2tf32(As[buf][mb    ][kk + tig + 4]);
                af[mf][3] = f2tf32(As[buf][mb + 8][kk + tig + 4]);
            }
#pragma unroll
            for (int nf = 0; nf < NF; nf++) {
                int nb = wn + nf * 8 + g;
                if (B_NT) {
                    bf[nf][0] = f2tf32(Bs[buf][nb][kk + tig    ]);
                    bf[nf][1] = f2tf32(Bs[buf][nb][kk + tig + 4]);
                } else {
                    bf[nf][0] = f2tf32(Bs[buf][kk + tig    ][nb]);
                    bf[nf][1] = f2tf32(Bs[buf][kk + tig + 4][nb]);
                }
            }
#pragma unroll
            for (int mf = 0; mf < MF; mf++)
#pragma unroll
                for (int nf = 0; nf < NF; nf++)
                    mma_tf32(acc[mf][nf], af[mf], bf[nf]);
        }
        __syncthreads();
        buf ^= 1;
    }

    // ---- epilogue ----
    const float* R = (EPI == EPI_BIAS_RES) ? resolve_c(Rx, Rid, 0) : nullptr;

    float s0[MF], s1[MF];
    if (EPI == EPI_EXP) {
#pragma unroll
        for (int mf = 0; mf < MF; mf++) { s0[mf] = 0.f; s1[mf] = 0.f; }
    }

#pragma unroll
    for (int mf = 0; mf < MF; mf++) {
#pragma unroll
        for (int nf = 0; nf < NF; nf++) {
            int r0 = bm + wm + mf * 16 + g;
            int r1 = r0 + 8;
            int c  = bn + wn + nf * 8 + tig * 2;
            float v0 = acc[mf][nf][0], v1 = acc[mf][nf][1];
            float v2 = acc[mf][nf][2], v3 = acc[mf][nf][3];
            if (EPI == EPI_BIAS || EPI == EPI_BIAS_RES || EPI == EPI_GELU) {
                float b0 = bias[c], b1 = bias[c + 1];
                v0 += b0; v1 += b1; v2 += b0; v3 += b1;
            }
            if (EPI == EPI_BIAS_RES) {
                float2 ra = *(const float2*)(R + (size_t)r0 * ldres + c);
                float2 rb = *(const float2*)(R + (size_t)r1 * ldres + c);
                v0 += ra.x; v1 += ra.y; v2 += rb.x; v3 += rb.y;
            }
            if (EPI == EPI_GELU) {
                v0 = gelu_f(v0); v1 = gelu_f(v1);
                v2 = gelu_f(v2); v3 = gelu_f(v3);
            }
            if (EPI == EPI_EXP) {
                v0 = (c     <= r0) ? __expf(v0 * scale) : 0.f;
                v1 = (c + 1 <= r0) ? __expf(v1 * scale) : 0.f;
                v2 = (c     <= r1) ? __expf(v2 * scale) : 0.f;
                v3 = (c + 1 <= r1) ? __expf(v3 * scale) : 0.f;
                s0[mf] += v0 + v1;
                s1[mf] += v2 + v3;
            }
            if (EPI == EPI_PV) {
                float i0 = 1.f / g_rsum[(size_t)z * SS + r0];
                float i1 = 1.f / g_rsum[(size_t)z * SS + r1];
                v0 *= i0; v1 *= i0; v2 *= i1; v3 *= i1;
            }
            float2 oa = {v0, v1}, ob = {v2, v3};
            *(float2*)(C + (size_t)r0 * ldc + c) = oa;
            *(float2*)(C + (size_t)r1 * ldc + c) = ob;
        }
    }

    if (EPI == EPI_EXP) {
        // reduce partial row sums over tig lanes (cols within warp), then warps
#pragma unroll
        for (int mf = 0; mf < MF; mf++) {
            s0[mf] += __shfl_xor_sync(0xffffffffu, s0[mf], 1);
            s0[mf] += __shfl_xor_sync(0xffffffffu, s0[mf], 2);
            s1[mf] += __shfl_xor_sync(0xffffffffu, s1[mf], 1);
            s1[mf] += __shfl_xor_sync(0xffffffffu, s1[mf], 2);
            if (tig == 0) {
                rowp[wnIdx][wm + mf * 16 + g    ] = s0[mf];
                rowp[wnIdx][wm + mf * 16 + g + 8] = s1[mf];
            }
        }
        __syncthreads();
        if (tid < BM) {
            float t = 0.f;
#pragma unroll
            for (int w = 0; w < WARPS_N; w++) t += rowp[w][tid];
            g_psum[((size_t)z * SS + bm + tid) * 8 + blockIdx.x] = t;
        }
    }
}

// ---------------------------------------------------------------------------
// Reduce per-tile partial sums -> row sums.  rows = BB*HH*SS = 65536
// ---------------------------------------------------------------------------
__global__ __launch_bounds__(256)
void reduce_psum_kernel()
{
    int r = blockIdx.x * 256 + threadIdx.x;       // global (z,row)
    int qr = r & (SS - 1);
    int nt = (qr >> 7) + 1;                        // tiles with bn <= row
    float s = 0.f;
    for (int t = 0; t < nt; t++) s += g_psum[(size_t)r * 8 + t];
    g_rsum[r] = s;
}

// ---------------------------------------------------------------------------
// att_weights[b,q,c] = (1/H) * sum_h probs[b,h,q,c] / rsum[b,h,q]
// One block per (b,q); reads only cols <= q (rest are exact zeros).
// ---------------------------------------------------------------------------
__global__ __launch_bounds__(256)
void mean_heads_kernel(float* __restrict__ out)
{
    int b = blockIdx.x >> 10;
    int q = blockIdx.x & (SS - 1);
    int t = threadIdx.x;

    __shared__ float inv[HH];
    if (t < HH) inv[t] = 1.f / g_rsum[((size_t)(b * HH + t)) * SS + q];
    __syncthreads();

    int KC4 = (q >> 2) + 1;                        // float4 chunks covering cols<=q
    float4 acc = {0.f, 0.f, 0.f, 0.f};
    if (t < KC4) {
#pragma unroll
        for (int h = 0; h < HH; h++) {
            const float* p = g_probs + (((size_t)(b * HH + h)) * SS + q) * SS + t * 4;
            float4 v = *(const float4*)p;
            float iv = inv[h];
            acc.x += v.x * iv; acc.y += v.y * iv;
            acc.z += v.z * iv; acc.w += v.w * iv;
        }
        const float ih = 1.f / HH;
        acc.x *= ih; acc.y *= ih; acc.z *= ih; acc.w *= ih;
    }
    *(float4*)(out + ((size_t)(b * SS + q)) * SS + t * 4) = acc;
}

// ---------------------------------------------------------------------------
// LayerNorm: one block per row of 1024 (256 threads, float4 each)
// ---------------------------------------------------------------------------
__global__ __launch_bounds__(256)
void ln_kernel(const float* __restrict__ xx, int xid,
               const float* __restrict__ g, const float* __restrict__ bt,
               int outid)
{
    const float* x = resolve_c(xx, xid, 0);
    float* out = scratch_ptr(outid);
    int row = blockIdx.x;
    const float* xr = x + (size_t)row * EE;
    int t = threadIdx.x;
    float4 v = *(const float4*)(xr + t * 4);
    float s  = v.x + v.y + v.z + v.w;
    float sq = v.x * v.x + v.y * v.y + v.z * v.z + v.w * v.w;
#pragma unroll
    for (int o = 16; o; o >>= 1) {
        s  += __shfl_xor_sync(0xffffffffu, s, o);
        sq += __shfl_xor_sync(0xffffffffu, sq, o);
    }
    __shared__ float ss[8], sqs[8];
    __shared__ float mu_s, rs_s;
    int w = t >> 5;
    if ((t & 31) == 0) { ss[w] = s; sqs[w] = sq; }
    __syncthreads();
    if (t == 0) {
        float S1 = 0.f, S2 = 0.f;
        for (int i = 0; i < 8; i++) { S1 += ss[i]; S2 += sqs[i]; }
        float mu  = S1 * (1.f / EE);
        float var = S2 * (1.f / EE) - mu * mu;
        mu_s = mu;
        rs_s = rsqrtf(var + 1e-5f);
    }
    __syncthreads();
    float mu = mu_s, rs = rs_s;
    float4 g4 = *(const float4*)(g + t * 4);
    float4 b4 = *(const float4*)(bt + t * 4);
    float4 o;
    o.x = (v.x - mu) * rs * g4.x + b4.x;
    o.y = (v.y - mu) * rs * g4.y + b4.y;
    o.z = (v.z - mu) * rs * g4.z + b4.z;
    o.w = (v.w - mu) * rs * g4.w + b4.w;
    *(float4*)(out + (size_t)row * EE + t * 4) = o;
}

// ---------------------------------------------------------------------------
// kernel_launch
// Inputs: x, causal_mask, ln1_g, ln1_b, ln2_g, ln2_b,
//   w_in, b_in, w_out, b_out, w_fc, b_fc, w_proj, b_proj
// Output: [x (4096*1024 f32)] then [att_weights (4*1024*1024 f32)]
// ---------------------------------------------------------------------------
extern "C" void kernel_launch(void* const* d_in, const int* in_sizes, int n_in,
                              void* d_out, int out_size)
{
    const float* x     = (const float*)d_in[0];
    const float* ln1g  = (const float*)d_in[2];
    const float* ln1b  = (const float*)d_in[3];
    const float* ln2g  = (const float*)d_in[4];
    const float* ln2b  = (const float*)d_in[5];
    const float* w_in  = (const float*)d_in[6];
    const float* b_in  = (const float*)d_in[7];
    const float* w_out = (const float*)d_in[8];
    const float* b_out = (const float*)d_in[9];
    const float* w_fc  = (const float*)d_in[10];
    const float* b_fc  = (const float*)d_in[11];
    const float* w_proj= (const float*)d_in[12];
    const float* b_proj= (const float*)d_in[13];

    float* outx = (float*)d_out;
    float* outw = outx + (size_t)NTOK * EE;

    const float scale = 0.125f; // 1/sqrt(64)

    // Scratch ids: 0=g_h 1=g_qkv 2=g_probs 3=g_att 4=g_x1 5=g_h2 6=g_fc

    // 1) h = LN1(x)
    ln_kernel<<<NTOK, 256>>>(x, -1, ln1g, ln1b, 0);

    // 2) qkv = h @ w_in^T + b_in    [4096 x 3072]
    mma_gemm<128, 128, 2, 4, EPI_BIAS, true, false>
        <<<dim3(3 * EE / 128, NTOK / 128, 1), 256>>>(
        nullptr, 0, 0,  w_in, -1, 0,  nullptr, 1,
        EE, EE, EE, 3 * EE, b_in, nullptr, -1, 0,
        0, 0, 0, 0, 0, 0, 1, 0.f);

    // 3) probs = exp(scale * q k^T) masked, + partial row sums  (batched b,h)
    mma_gemm<128, 128, 2, 4, EPI_EXP, true, false>
        <<<dim3(SS / 128, SS / 128, BB * HH), 256>>>(
        nullptr, 1, 0,  nullptr, 1, EE,  nullptr, 2,
        DH, 3 * EE, 3 * EE, SS, nullptr, nullptr, -1, 0,
        (long)SS * 3 * EE, DH, (long)SS * 3 * EE, DH,
        (long)HH * SS * SS, (long)SS * SS, HH, scale);

    // 4) row sums
    reduce_psum_kernel<<<BB * HH * SS / 256, 256>>>();

    // 5) att_weights = mean over heads of normalized probs
    mean_heads_kernel<<<BB * SS, 256>>>(outw);

    // 6) att = (probs @ v) / rsum   (batched b,h; triangular K)
    mma_gemm<128, 64, 4, 2, EPI_PV, false, true>
        <<<dim3(1, SS / 128, BB * HH), 256>>>(
        nullptr, 2, 0,  nullptr, 1, 2 * EE,  nullptr, 3,
        SS, SS, 3 * EE, EE, nullptr, nullptr, -1, 0,
        (long)HH * SS * SS, (long)SS * SS, (long)SS * 3 * EE, DH,
        (long)SS * EE, DH, HH, 0.f);

    // 7) x1 = x + att @ w_out^T + b_out
    mma_gemm<128, 128, 2, 4, EPI_BIAS_RES, true, false>
        <<<dim3(EE / 128, NTOK / 128, 1), 256>>>(
        nullptr, 3, 0,  w_out, -1, 0,  nullptr, 4,
        EE, EE, EE, EE, b_out, x, -1, EE,
        0, 0, 0, 0, 0, 0, 1, 0.f);

    // 8) h2 = LN2(x1)
    ln_kernel<<<NTOK, 256>>>(nullptr, 4, ln2g, ln2b, 5);

    // 9) fc = gelu(h2 @ w_fc^T + b_fc)   [4096 x 4096]
    mma_gemm<128, 128, 2, 4, EPI_GELU, true, false>
        <<<dim3(4 * EE / 128, NTOK / 128, 1), 256>>>(
        nullptr, 5, 0,  w_fc, -1, 0,  nullptr, 6,
        EE, EE, EE, 4 * EE, b_fc, nullptr, -1, 0,
        0, 0, 0, 0, 0, 0, 1, 0.f);

    // 10) out_x = x1 + fc @ w_proj^T + b_proj
    mma_gemm<128, 128, 2, 4, EPI_BIAS_RES, true, false>
        <<<dim3(EE / 128, NTOK / 128, 1), 256>>>(
        nullptr, 6, 0,  w_proj, -1, 0,  outx, -1,
        4 * EE, 4 * EE, 4 * EE, EE, b_proj, nullptr, 4, EE,
        0, 0, 0, 0, 0, 0, 1, 0.f);
}